// round 7
// baseline (speedup 1.0000x reference)
#include <cuda_runtime.h>

// VolGeoNet trilinear interp: region-binned points + persistent-CTA
// L1-cached gathers.
// - 16^3 region bins (4 cells/axis), points counting-sorted by bin.
// - Work item = (channel-half, bin); 2*4096 = 8192 items.
// - 592 persistent CTAs (4/SM), each sweeps ~14 consecutive items
//   (half-major => consecutive z-adjacent bins, 62.5KB L1 working set
//   with 25-row face reuse between items). Single wave.
// Inputs: x [B,3] f32, grid_value [65^3,1] f32, grid_feature [65^3,256] f32.
// Output: concat(out [B,1], feat [B,256]) float, out first.

#define N_GRID 64
#define N1 65
#define W_FEAT 256
#define MAXB 262144
#define NBINS (16 * 16 * 16)
#define NITEMS (2 * NBINS)
#define GRID_MAIN 592

__device__ int    g_hist[NBINS];          // zero at entry to every call (see scatter)
__device__ int    g_binstart[NBINS + 1];
__device__ int    g_key[MAXB];
__device__ int    g_rank[MAXB];
__device__ float4 g_xs[MAXB];             // sorted (x,y,z, bitcast point-index)

__global__ void histo_kernel(const float* __restrict__ x, int B)
{
    int p = blockIdx.x * blockDim.x + threadIdx.x;
    if (p >= B) return;
    const float rx = (x[p * 3 + 0] + 1.0f) * 32.0f;
    const float ry = (x[p * 3 + 1] + 1.0f) * 32.0f;
    const float rz = (x[p * 3 + 2] + 1.0f) * 32.0f;
    int ix = (int)floorf(rx); ix = ix < 0 ? 0 : (ix > 63 ? 63 : ix);
    int iy = (int)floorf(ry); iy = iy < 0 ? 0 : (iy > 63 ? 63 : iy);
    int iz = (int)floorf(rz); iz = iz < 0 ? 0 : (iz > 63 ? 63 : iz);
    int key = ((ix >> 2) * 16 + (iy >> 2)) * 16 + (iz >> 2);
    g_key[p] = key;
    g_rank[p] = atomicAdd(&g_hist[key], 1);
}

// Single block, 1024 threads, 4 bins each -> exclusive scan over 4096 bins.
__global__ void __launch_bounds__(1024) scan_kernel()
{
    __shared__ int s[1024];
    const int t = threadIdx.x;
    const int base = t * 4;
    int local[4];
    int sum = 0;
#pragma unroll
    for (int i = 0; i < 4; i++) {
        local[i] = sum;
        sum += g_hist[base + i];
    }
    s[t] = sum;
    __syncthreads();
    for (int off = 1; off < 1024; off <<= 1) {
        int v = 0;
        if (t >= off) v = s[t - off];
        __syncthreads();
        if (t >= off) s[t] += v;
        __syncthreads();
    }
    const int prefix = (t == 0) ? 0 : s[t - 1];
#pragma unroll
    for (int i = 0; i < 4; i++)
        g_binstart[base + i] = prefix + local[i];
    if (t == 1023) g_binstart[NBINS] = s[1023];   // total
}

// Scatter sorted points; also re-zero g_hist so it is zero at entry to the
// next kernel_launch call (deterministic invariant; g_hist is statically
// zero-initialized before the first call, and no later kernel reads it).
__global__ void scatter_kernel(const float* __restrict__ x, int B)
{
    int p = blockIdx.x * blockDim.x + threadIdx.x;
    if (p >= B) return;
    const int dst = g_binstart[g_key[p]] + g_rank[p];
    g_xs[dst] = make_float4(x[p * 3 + 0], x[p * 3 + 1], x[p * 3 + 2],
                            __int_as_float(p));
    if (p < NBINS) g_hist[p] = 0;
}

// ──────────────────────────────────────────────────────────────────────────
// Persistent main kernel: each CTA handles items [cta*chunk, (cta+1)*chunk),
// item = half*NBINS + bin (half-major -> consecutive z-adjacent bins).
__global__ void __launch_bounds__(256) trilerp_persist_kernel(
    const float* __restrict__ gv,
    const float* __restrict__ gf,
    float* __restrict__ out_val,   // [B]
    float* __restrict__ out_feat,  // [B, 256]
    int chunk)
{
    const int tid  = threadIdx.x;
    const int wid  = tid >> 5;
    const int lane = tid & 31;

    const int goffs[8] = { 0, 1, N1, N1 + 1,
                           N1 * N1, N1 * N1 + 1, N1 * N1 + N1, N1 * N1 + N1 + 1 };

    const int item0 = blockIdx.x * chunk;

    for (int j = 0; j < chunk; j++) {
        const int item = item0 + j;
        if (item >= NITEMS) return;
        const int half = item >> 12;          // item / NBINS
        const int bin  = item & (NBINS - 1);

        const int start = g_binstart[bin];
        const int count = g_binstart[bin + 1] - start;
        if (count == 0) continue;

        const int coff = (half << 5) + lane;  // float4 column within 1KB row

        for (int i = wid; i < count; i += 8) {
            const float4 xp = __ldcs(&g_xs[start + i]);
            const int p = __float_as_int(xp.w);

            const float rx = (xp.x + 1.0f) * 32.0f;
            const float ry = (xp.y + 1.0f) * 32.0f;
            const float rz = (xp.z + 1.0f) * 32.0f;

            const bool valid = (rx >= 0.0f) && (rx <= 64.0f) &&
                               (ry >= 0.0f) && (ry <= 64.0f) &&
                               (rz >= 0.0f) && (rz <= 64.0f);
            const float vmask = valid ? 1.0f : 0.0f;

            int ix = (int)floorf(rx); ix = ix < 0 ? 0 : (ix > 63 ? 63 : ix);
            int iy = (int)floorf(ry); iy = iy < 0 ? 0 : (iy > 63 ? 63 : iy);
            int iz = (int)floorf(rz); iz = iz < 0 ? 0 : (iz > 63 ? 63 : iz);

            const float tx = rx - (float)ix;
            const float ty = ry - (float)iy;
            const float tz = rz - (float)iz;

            const float wx0 = 1.0f - tx, wy0 = 1.0f - ty, wz0 = 1.0f - tz;
            float w[8];
            w[0] = wx0 * wy0 * wz0;
            w[1] = wx0 * wy0 * tz;
            w[2] = wx0 * ty  * wz0;
            w[3] = wx0 * ty  * tz;
            w[4] = tx  * wy0 * wz0;
            w[5] = tx  * wy0 * tz;
            w[6] = tx  * ty  * wz0;
            w[7] = tx  * ty  * tz;

            const int base = (ix * N1 + iy) * N1 + iz;

            if (half == 0) {
                float gvv = 0.0f;
                if (lane < 8) gvv = w[lane] * __ldg(gv + base + goffs[lane]);
                gvv += __shfl_xor_sync(0xffffffffu, gvv, 4);
                gvv += __shfl_xor_sync(0xffffffffu, gvv, 2);
                gvv += __shfl_xor_sync(0xffffffffu, gvv, 1);
                if (lane == 0) out_val[p] = gvv * vmask;
            }

            // 8 independent LDG.128 (L1-resident after first touch per row).
            float4 f[8];
#pragma unroll
            for (int c = 0; c < 8; c++)
                f[c] = __ldg((const float4*)(gf + (size_t)(base + goffs[c]) * W_FEAT) + coff);

            float a0 = 0.f, a1 = 0.f, a2 = 0.f, a3 = 0.f;
#pragma unroll
            for (int c = 0; c < 8; c++) {
                const float wc = w[c];
                a0 = fmaf(wc, f[c].x, a0);
                a1 = fmaf(wc, f[c].y, a1);
                a2 = fmaf(wc, f[c].z, a2);
                a3 = fmaf(wc, f[c].w, a3);
            }

            float4* frow = (float4*)(out_feat + (size_t)p * W_FEAT);
            __stcs(frow + coff,
                   make_float4(a0 * vmask, a1 * vmask, a2 * vmask, a3 * vmask));
        }
    }
}

// Fallback (B > MAXB): direct global-gather version, unsorted.
__global__ void __launch_bounds__(256) trilerp_kernel(
    const float* __restrict__ x,
    const float* __restrict__ gv,
    const float* __restrict__ gf,
    float* __restrict__ out_val,
    float* __restrict__ out_feat,
    int B)
{
    const int p = (blockIdx.x * blockDim.x + threadIdx.x) >> 5;
    const int lane = threadIdx.x & 31;
    if (p >= B) return;

    const float rx = (__ldg(x + p * 3 + 0) + 1.0f) * 32.0f;
    const float ry = (__ldg(x + p * 3 + 1) + 1.0f) * 32.0f;
    const float rz = (__ldg(x + p * 3 + 2) + 1.0f) * 32.0f;
    const bool valid = (rx >= 0.0f) && (rx <= 64.0f) && (ry >= 0.0f) &&
                       (ry <= 64.0f) && (rz >= 0.0f) && (rz <= 64.0f);
    const float vmask = valid ? 1.0f : 0.0f;
    int ix = (int)floorf(rx); ix = ix < 0 ? 0 : (ix > 63 ? 63 : ix);
    int iy = (int)floorf(ry); iy = iy < 0 ? 0 : (iy > 63 ? 63 : iy);
    int iz = (int)floorf(rz); iz = iz < 0 ? 0 : (iz > 63 ? 63 : iz);
    const float tx = rx - ix, ty = ry - iy, tz = rz - iz;
    const int base = (ix * N1 + iy) * N1 + iz;
    const float wx0 = 1.0f - tx, wy0 = 1.0f - ty, wz0 = 1.0f - tz;
    float w[8] = { wx0*wy0*wz0, wx0*wy0*tz, wx0*ty*wz0, wx0*ty*tz,
                   tx*wy0*wz0,  tx*wy0*tz,  tx*ty*wz0,  tx*ty*tz };
    const int offs[8] = { 0, 1, N1, N1+1, N1*N1, N1*N1+1, N1*N1+N1, N1*N1+N1+1 };

    float gvv = 0.0f;
    if (lane < 8) gvv = w[lane] * __ldg(gv + base + offs[lane]);
    gvv += __shfl_xor_sync(0xffffffffu, gvv, 4);
    gvv += __shfl_xor_sync(0xffffffffu, gvv, 2);
    gvv += __shfl_xor_sync(0xffffffffu, gvv, 1);
    if (lane == 0) out_val[p] = gvv * vmask;

    float a0=0,a1=0,a2=0,a3=0,b0=0,b1=0,b2=0,b3=0;
#pragma unroll
    for (int c = 0; c < 8; c++) {
        const float4* row = (const float4*)(gf + (size_t)(base + offs[c]) * W_FEAT);
        const float4 fa = __ldg(row + lane);
        const float4 fb = __ldg(row + lane + 32);
        const float wc = w[c];
        a0 = fmaf(wc, fa.x, a0); a1 = fmaf(wc, fa.y, a1);
        a2 = fmaf(wc, fa.z, a2); a3 = fmaf(wc, fa.w, a3);
        b0 = fmaf(wc, fb.x, b0); b1 = fmaf(wc, fb.y, b1);
        b2 = fmaf(wc, fb.z, b2); b3 = fmaf(wc, fb.w, b3);
    }
    float4* frow = (float4*)(out_feat + (size_t)p * W_FEAT);
    frow[lane]      = make_float4(a0*vmask, a1*vmask, a2*vmask, a3*vmask);
    frow[lane + 32] = make_float4(b0*vmask, b1*vmask, b2*vmask, b3*vmask);
}

extern "C" void kernel_launch(void* const* d_in, const int* in_sizes, int n_in,
                              void* d_out, int out_size)
{
    const float* x  = (const float*)d_in[0];
    const float* gv = (const float*)d_in[1];
    const float* gf = (const float*)d_in[2];
    float* out = (float*)d_out;

    const int B = in_sizes[0] / 3;
    float* out_val  = out;        // [B]
    float* out_feat = out + B;    // [B, 256]

    if (B <= MAXB && B >= NBINS) {
        const int chunk = (NITEMS + GRID_MAIN - 1) / GRID_MAIN;   // 14
        histo_kernel<<<(B + 255) / 256, 256>>>(x, B);
        scan_kernel<<<1, 1024>>>();
        scatter_kernel<<<(B + 255) / 256, 256>>>(x, B);
        trilerp_persist_kernel<<<GRID_MAIN, 256>>>(gv, gf, out_val, out_feat, chunk);
    } else {
        const int blocks = (B + 7) / 8;
        trilerp_kernel<<<blocks, 256>>>(x, gv, gf, out_val, out_feat, B);
    }
}

// round 8
// speedup vs baseline: 1.3309x; 1.3309x over previous
#include <cuda_runtime.h>

// VolGeoNet trilinear interp: region-binned points + persistent work-stealing
// CTAs with L1-cached gathers and software-pipelined point loads.
// - 16^3 region bins (4 cells/axis), points counting-sorted by bin.
// - Work item = (channel-half, bin); 2*4096 = 8192 items, dispatched via a
//   global atomic counter (perfect balance, single wave).
// - 888 CTAs x 256 thr = 6 CTAs/SM @ 40 regs -> 48 warps/SM.
// Inputs: x [B,3] f32, grid_value [65^3,1] f32, grid_feature [65^3,256] f32.
// Output: concat(out [B,1], feat [B,256]) float, out first.

#define N_GRID 64
#define N1 65
#define W_FEAT 256
#define MAXB 262144
#define NBINS (16 * 16 * 16)
#define NITEMS (2 * NBINS)
#define GRID_MAIN 888

__device__ int    g_hist[NBINS];          // zero at entry to every call (see scatter)
__device__ int    g_binstart[NBINS + 1];
__device__ int    g_key[MAXB];
__device__ int    g_rank[MAXB];
__device__ float4 g_xs[MAXB];             // sorted (x,y,z, bitcast point-index)
__device__ int    g_item;                 // work-stealing cursor (reset by histo)

__global__ void histo_kernel(const float* __restrict__ x, int B)
{
    int p = blockIdx.x * blockDim.x + threadIdx.x;
    if (p == 0) g_item = 0;               // reset stealing cursor for this call
    if (p >= B) return;
    const float rx = (x[p * 3 + 0] + 1.0f) * 32.0f;
    const float ry = (x[p * 3 + 1] + 1.0f) * 32.0f;
    const float rz = (x[p * 3 + 2] + 1.0f) * 32.0f;
    int ix = (int)floorf(rx); ix = ix < 0 ? 0 : (ix > 63 ? 63 : ix);
    int iy = (int)floorf(ry); iy = iy < 0 ? 0 : (iy > 63 ? 63 : iy);
    int iz = (int)floorf(rz); iz = iz < 0 ? 0 : (iz > 63 ? 63 : iz);
    int key = ((ix >> 2) * 16 + (iy >> 2)) * 16 + (iz >> 2);
    g_key[p] = key;
    g_rank[p] = atomicAdd(&g_hist[key], 1);
}

// Single block, 1024 threads, 4 bins each -> exclusive scan over 4096 bins.
__global__ void __launch_bounds__(1024) scan_kernel()
{
    __shared__ int s[1024];
    const int t = threadIdx.x;
    const int base = t * 4;
    int local[4];
    int sum = 0;
#pragma unroll
    for (int i = 0; i < 4; i++) {
        local[i] = sum;
        sum += g_hist[base + i];
    }
    s[t] = sum;
    __syncthreads();
    for (int off = 1; off < 1024; off <<= 1) {
        int v = 0;
        if (t >= off) v = s[t - off];
        __syncthreads();
        if (t >= off) s[t] += v;
        __syncthreads();
    }
    const int prefix = (t == 0) ? 0 : s[t - 1];
#pragma unroll
    for (int i = 0; i < 4; i++)
        g_binstart[base + i] = prefix + local[i];
    if (t == 1023) g_binstart[NBINS] = s[1023];   // total
}

// Scatter sorted points; re-zero g_hist for the next kernel_launch call.
__global__ void scatter_kernel(const float* __restrict__ x, int B)
{
    int p = blockIdx.x * blockDim.x + threadIdx.x;
    if (p >= B) return;
    const int dst = g_binstart[g_key[p]] + g_rank[p];
    g_xs[dst] = make_float4(x[p * 3 + 0], x[p * 3 + 1], x[p * 3 + 2],
                            __int_as_float(p));
    if (p < NBINS) g_hist[p] = 0;
}

// ──────────────────────────────────────────────────────────────────────────
// Persistent work-stealing main kernel.
__global__ void __launch_bounds__(256) trilerp_persist_kernel(
    const float* __restrict__ gv,
    const float* __restrict__ gf,
    float* __restrict__ out_val,   // [B]
    float* __restrict__ out_feat)  // [B, 256]
{
    __shared__ int s_item;
    const int tid  = threadIdx.x;
    const int wid  = tid >> 5;
    const int lane = tid & 31;

    const int goffs[8] = { 0, 1, N1, N1 + 1,
                           N1 * N1, N1 * N1 + 1, N1 * N1 + N1, N1 * N1 + N1 + 1 };

    for (;;) {
        if (tid == 0) s_item = atomicAdd(&g_item, 1);
        __syncthreads();
        const int item = s_item;
        __syncthreads();
        if (item >= NITEMS) return;

        const int half = item >> 12;          // item / NBINS
        const int bin  = item & (NBINS - 1);

        const int start = g_binstart[bin];
        const int count = g_binstart[bin + 1] - start;
        if (count == 0) continue;

        const int coff = (half << 5) + lane;  // float4 column within 1KB row

        int i = wid;
        if (i < count) {
            float4 xp = __ldcs(&g_xs[start + i]);
            while (i < count) {
                const int inext = i + 8;
                float4 xpn;
                if (inext < count) xpn = __ldcs(&g_xs[start + inext]);

                const int p = __float_as_int(xp.w);

                const float rx = (xp.x + 1.0f) * 32.0f;
                const float ry = (xp.y + 1.0f) * 32.0f;
                const float rz = (xp.z + 1.0f) * 32.0f;

                const bool valid = (rx >= 0.0f) && (rx <= 64.0f) &&
                                   (ry >= 0.0f) && (ry <= 64.0f) &&
                                   (rz >= 0.0f) && (rz <= 64.0f);
                const float vmask = valid ? 1.0f : 0.0f;

                int ix = (int)floorf(rx); ix = ix < 0 ? 0 : (ix > 63 ? 63 : ix);
                int iy = (int)floorf(ry); iy = iy < 0 ? 0 : (iy > 63 ? 63 : iy);
                int iz = (int)floorf(rz); iz = iz < 0 ? 0 : (iz > 63 ? 63 : iz);

                const float tx = rx - (float)ix;
                const float ty = ry - (float)iy;
                const float tz = rz - (float)iz;

                const float wx0 = 1.0f - tx, wy0 = 1.0f - ty, wz0 = 1.0f - tz;
                float w[8];
                w[0] = wx0 * wy0 * wz0;
                w[1] = wx0 * wy0 * tz;
                w[2] = wx0 * ty  * wz0;
                w[3] = wx0 * ty  * tz;
                w[4] = tx  * wy0 * wz0;
                w[5] = tx  * wy0 * tz;
                w[6] = tx  * ty  * wz0;
                w[7] = tx  * ty  * tz;

                const int base = (ix * N1 + iy) * N1 + iz;

                // 8 independent LDG.128 (L1-resident after first touch per row).
                float4 f[8];
#pragma unroll
                for (int c = 0; c < 8; c++)
                    f[c] = __ldg((const float4*)(gf + (size_t)(base + goffs[c]) * W_FEAT) + coff);

                if (half == 0) {
                    float gvv = 0.0f;
                    if (lane < 8) gvv = w[lane] * __ldg(gv + base + goffs[lane]);
                    gvv += __shfl_xor_sync(0xffffffffu, gvv, 4);
                    gvv += __shfl_xor_sync(0xffffffffu, gvv, 2);
                    gvv += __shfl_xor_sync(0xffffffffu, gvv, 1);
                    if (lane == 0) out_val[p] = gvv * vmask;
                }

                float a0 = 0.f, a1 = 0.f, a2 = 0.f, a3 = 0.f;
#pragma unroll
                for (int c = 0; c < 8; c++) {
                    const float wc = w[c];
                    a0 = fmaf(wc, f[c].x, a0);
                    a1 = fmaf(wc, f[c].y, a1);
                    a2 = fmaf(wc, f[c].z, a2);
                    a3 = fmaf(wc, f[c].w, a3);
                }

                float4* frow = (float4*)(out_feat + (size_t)p * W_FEAT);
                __stcs(frow + coff,
                       make_float4(a0 * vmask, a1 * vmask, a2 * vmask, a3 * vmask));

                xp = xpn;
                i = inext;
            }
        }
    }
}

// Fallback (B > MAXB or tiny B): direct global-gather version, unsorted.
__global__ void __launch_bounds__(256) trilerp_kernel(
    const float* __restrict__ x,
    const float* __restrict__ gv,
    const float* __restrict__ gf,
    float* __restrict__ out_val,
    float* __restrict__ out_feat,
    int B)
{
    const int p = (blockIdx.x * blockDim.x + threadIdx.x) >> 5;
    const int lane = threadIdx.x & 31;
    if (p >= B) return;

    const float rx = (__ldg(x + p * 3 + 0) + 1.0f) * 32.0f;
    const float ry = (__ldg(x + p * 3 + 1) + 1.0f) * 32.0f;
    const float rz = (__ldg(x + p * 3 + 2) + 1.0f) * 32.0f;
    const bool valid = (rx >= 0.0f) && (rx <= 64.0f) && (ry >= 0.0f) &&
                       (ry <= 64.0f) && (rz >= 0.0f) && (rz <= 64.0f);
    const float vmask = valid ? 1.0f : 0.0f;
    int ix = (int)floorf(rx); ix = ix < 0 ? 0 : (ix > 63 ? 63 : ix);
    int iy = (int)floorf(ry); iy = iy < 0 ? 0 : (iy > 63 ? 63 : iy);
    int iz = (int)floorf(rz); iz = iz < 0 ? 0 : (iz > 63 ? 63 : iz);
    const float tx = rx - ix, ty = ry - iy, tz = rz - iz;
    const int base = (ix * N1 + iy) * N1 + iz;
    const float wx0 = 1.0f - tx, wy0 = 1.0f - ty, wz0 = 1.0f - tz;
    float w[8] = { wx0*wy0*wz0, wx0*wy0*tz, wx0*ty*wz0, wx0*ty*tz,
                   tx*wy0*wz0,  tx*wy0*tz,  tx*ty*wz0,  tx*ty*tz };
    const int offs[8] = { 0, 1, N1, N1+1, N1*N1, N1*N1+1, N1*N1+N1, N1*N1+N1+1 };

    float gvv = 0.0f;
    if (lane < 8) gvv = w[lane] * __ldg(gv + base + offs[lane]);
    gvv += __shfl_xor_sync(0xffffffffu, gvv, 4);
    gvv += __shfl_xor_sync(0xffffffffu, gvv, 2);
    gvv += __shfl_xor_sync(0xffffffffu, gvv, 1);
    if (lane == 0) out_val[p] = gvv * vmask;

    float a0=0,a1=0,a2=0,a3=0,b0=0,b1=0,b2=0,b3=0;
#pragma unroll
    for (int c = 0; c < 8; c++) {
        const float4* row = (const float4*)(gf + (size_t)(base + offs[c]) * W_FEAT);
        const float4 fa = __ldg(row + lane);
        const float4 fb = __ldg(row + lane + 32);
        const float wc = w[c];
        a0 = fmaf(wc, fa.x, a0); a1 = fmaf(wc, fa.y, a1);
        a2 = fmaf(wc, fa.z, a2); a3 = fmaf(wc, fa.w, a3);
        b0 = fmaf(wc, fb.x, b0); b1 = fmaf(wc, fb.y, b1);
        b2 = fmaf(wc, fb.z, b2); b3 = fmaf(wc, fb.w, b3);
    }
    float4* frow = (float4*)(out_feat + (size_t)p * W_FEAT);
    frow[lane]      = make_float4(a0*vmask, a1*vmask, a2*vmask, a3*vmask);
    frow[lane + 32] = make_float4(b0*vmask, b1*vmask, b2*vmask, b3*vmask);
}

extern "C" void kernel_launch(void* const* d_in, const int* in_sizes, int n_in,
                              void* d_out, int out_size)
{
    const float* x  = (const float*)d_in[0];
    const float* gv = (const float*)d_in[1];
    const float* gf = (const float*)d_in[2];
    float* out = (float*)d_out;

    const int B = in_sizes[0] / 3;
    float* out_val  = out;        // [B]
    float* out_feat = out + B;    // [B, 256]

    if (B <= MAXB && B >= NBINS) {
        histo_kernel<<<(B + 255) / 256, 256>>>(x, B);
        scan_kernel<<<1, 1024>>>();
        scatter_kernel<<<(B + 255) / 256, 256>>>(x, B);
        trilerp_persist_kernel<<<GRID_MAIN, 256>>>(gv, gf, out_val, out_feat);
    } else {
        const int blocks = (B + 7) / 8;
        trilerp_kernel<<<blocks, 256>>>(x, gv, gf, out_val, out_feat, B);
    }
}

// round 9
// speedup vs baseline: 1.4190x; 1.0662x over previous
#include <cuda_runtime.h>

// VolGeoNet trilinear interp: region-binned points + persistent work-stealing
// CTAs with L1-cached gathers. Low-register variant for 48-warp/SM residency.
// - 16^3 region bins (4 cells/axis), points counting-sorted by bin.
// - Work item = (channel-half, bin); 2*4096 = 8192 items via atomic cursor.
// - 1776 CTAs x 128 thr = 12 CTAs/SM (@ <=42 regs) -> 48 warps/SM, 1 wave.
// Inputs: x [B,3] f32, grid_value [65^3,1] f32, grid_feature [65^3,256] f32.
// Output: concat(out [B,1], feat [B,256]) float, out first.

#define N_GRID 64
#define N1 65
#define W_FEAT 256
#define MAXB 262144
#define NBINS (16 * 16 * 16)
#define NITEMS (2 * NBINS)
#define GRID_MAIN 1776

__device__ int    g_hist[NBINS];          // zero at entry to every call (see scatter)
__device__ int    g_binstart[NBINS + 1];
__device__ int    g_key[MAXB];
__device__ int    g_rank[MAXB];
__device__ float4 g_xs[MAXB];             // sorted (x,y,z, bitcast point-index)
__device__ int    g_item;                 // work-stealing cursor (reset by histo)

__global__ void histo_kernel(const float* __restrict__ x, int B)
{
    int p = blockIdx.x * blockDim.x + threadIdx.x;
    if (p == 0) g_item = 0;               // reset stealing cursor for this call
    if (p >= B) return;
    const float rx = (x[p * 3 + 0] + 1.0f) * 32.0f;
    const float ry = (x[p * 3 + 1] + 1.0f) * 32.0f;
    const float rz = (x[p * 3 + 2] + 1.0f) * 32.0f;
    int ix = (int)floorf(rx); ix = ix < 0 ? 0 : (ix > 63 ? 63 : ix);
    int iy = (int)floorf(ry); iy = iy < 0 ? 0 : (iy > 63 ? 63 : iy);
    int iz = (int)floorf(rz); iz = iz < 0 ? 0 : (iz > 63 ? 63 : iz);
    int key = ((ix >> 2) * 16 + (iy >> 2)) * 16 + (iz >> 2);
    g_key[p] = key;
    g_rank[p] = atomicAdd(&g_hist[key], 1);
}

// Single block, 1024 threads, 4 bins each -> exclusive scan over 4096 bins.
__global__ void __launch_bounds__(1024) scan_kernel()
{
    __shared__ int s[1024];
    const int t = threadIdx.x;
    const int base = t * 4;
    int local[4];
    int sum = 0;
#pragma unroll
    for (int i = 0; i < 4; i++) {
        local[i] = sum;
        sum += g_hist[base + i];
    }
    s[t] = sum;
    __syncthreads();
    for (int off = 1; off < 1024; off <<= 1) {
        int v = 0;
        if (t >= off) v = s[t - off];
        __syncthreads();
        if (t >= off) s[t] += v;
        __syncthreads();
    }
    const int prefix = (t == 0) ? 0 : s[t - 1];
#pragma unroll
    for (int i = 0; i < 4; i++)
        g_binstart[base + i] = prefix + local[i];
    if (t == 1023) g_binstart[NBINS] = s[1023];   // total
}

// Scatter sorted points; re-zero g_hist for the next kernel_launch call.
__global__ void scatter_kernel(const float* __restrict__ x, int B)
{
    int p = blockIdx.x * blockDim.x + threadIdx.x;
    if (p >= B) return;
    const int dst = g_binstart[g_key[p]] + g_rank[p];
    g_xs[dst] = make_float4(x[p * 3 + 0], x[p * 3 + 1], x[p * 3 + 2],
                            __int_as_float(p));
    if (p < NBINS) g_hist[p] = 0;
}

// ──────────────────────────────────────────────────────────────────────────
// Persistent work-stealing main kernel (128 threads, low regs).
__global__ void __launch_bounds__(128, 12) trilerp_persist_kernel(
    const float* __restrict__ gv,
    const float* __restrict__ gf,
    float* __restrict__ out_val,   // [B]
    float* __restrict__ out_feat)  // [B, 256]
{
    __shared__ int s_item;
    const int tid  = threadIdx.x;
    const int wid  = tid >> 5;
    const int lane = tid & 31;

    for (;;) {
        if (tid == 0) s_item = atomicAdd(&g_item, 1);
        __syncthreads();
        const int item = s_item;
        __syncthreads();
        if (item >= NITEMS) return;

        const int half = item >> 12;          // item / NBINS
        const int bin  = item & (NBINS - 1);

        const int start = g_binstart[bin];
        const int count = g_binstart[bin + 1] - start;
        if (count == 0) continue;

        const int coff = (half << 5) + lane;  // float4 column within 1KB row

        for (int i = wid; i < count; i += 4) {
            const float4 xp = __ldcs(&g_xs[start + i]);
            const int p = __float_as_int(xp.w);

            const float rx = (xp.x + 1.0f) * 32.0f;
            const float ry = (xp.y + 1.0f) * 32.0f;
            const float rz = (xp.z + 1.0f) * 32.0f;

            const bool valid = (rx >= 0.0f) && (rx <= 64.0f) &&
                               (ry >= 0.0f) && (ry <= 64.0f) &&
                               (rz >= 0.0f) && (rz <= 64.0f);
            const float vmask = valid ? 1.0f : 0.0f;

            int ix = (int)floorf(rx); ix = ix < 0 ? 0 : (ix > 63 ? 63 : ix);
            int iy = (int)floorf(ry); iy = iy < 0 ? 0 : (iy > 63 ? 63 : iy);
            int iz = (int)floorf(rz); iz = iz < 0 ? 0 : (iz > 63 ? 63 : iz);

            const float tx = rx - (float)ix;
            const float ty = ry - (float)iy;
            const float tz = rz - (float)iz;
            const float wx0 = 1.0f - tx, wy0 = 1.0f - ty, wz0 = 1.0f - tz;

            // y-z weight products shared by both x-planes.
            const float wyz0 = wy0 * wz0;
            const float wyz1 = wy0 * tz;
            const float wyz2 = ty  * wz0;
            const float wyz3 = ty  * tz;

            const int base = (ix * N1 + iy) * N1 + iz;
            const float4* rlo = (const float4*)(gf + (size_t)base * W_FEAT) + coff;
            const float4* rhi = rlo + (size_t)(N1 * N1) * (W_FEAT / 4);

            // x-low plane: corners (0,0,0),(0,0,1),(0,1,0),(0,1,1)
            {
                const float4 f0 = __ldg(rlo);
                const float4 f1 = __ldg(rlo + (W_FEAT / 4));
                const float4 f2 = __ldg(rlo + N1 * (W_FEAT / 4));
                const float4 f3 = __ldg(rlo + (N1 + 1) * (W_FEAT / 4));
                float s0, s1, s2, s3;
                s0 = wyz0 * f0.x; s1 = wyz0 * f0.y; s2 = wyz0 * f0.z; s3 = wyz0 * f0.w;
                s0 = fmaf(wyz1, f1.x, s0); s1 = fmaf(wyz1, f1.y, s1);
                s2 = fmaf(wyz1, f1.z, s2); s3 = fmaf(wyz1, f1.w, s3);
                s0 = fmaf(wyz2, f2.x, s0); s1 = fmaf(wyz2, f2.y, s1);
                s2 = fmaf(wyz2, f2.z, s2); s3 = fmaf(wyz2, f2.w, s3);
                s0 = fmaf(wyz3, f3.x, s0); s1 = fmaf(wyz3, f3.y, s1);
                s2 = fmaf(wyz3, f3.z, s2); s3 = fmaf(wyz3, f3.w, s3);
                // stash x-low partial scaled by wx0 in s*
                s0 *= wx0; s1 *= wx0; s2 *= wx0; s3 *= wx0;

                // x-high plane
                const float4 g0 = __ldg(rhi);
                const float4 g1 = __ldg(rhi + (W_FEAT / 4));
                const float4 g2 = __ldg(rhi + N1 * (W_FEAT / 4));
                const float4 g3 = __ldg(rhi + (N1 + 1) * (W_FEAT / 4));
                float u0, u1, u2, u3;
                u0 = wyz0 * g0.x; u1 = wyz0 * g0.y; u2 = wyz0 * g0.z; u3 = wyz0 * g0.w;
                u0 = fmaf(wyz1, g1.x, u0); u1 = fmaf(wyz1, g1.y, u1);
                u2 = fmaf(wyz1, g1.z, u2); u3 = fmaf(wyz1, g1.w, u3);
                u0 = fmaf(wyz2, g2.x, u0); u1 = fmaf(wyz2, g2.y, u1);
                u2 = fmaf(wyz2, g2.z, u2); u3 = fmaf(wyz2, g2.w, u3);
                u0 = fmaf(wyz3, g3.x, u0); u1 = fmaf(wyz3, g3.y, u1);
                u2 = fmaf(wyz3, g3.z, u2); u3 = fmaf(wyz3, g3.w, u3);

                s0 = fmaf(tx, u0, s0); s1 = fmaf(tx, u1, s1);
                s2 = fmaf(tx, u2, s2); s3 = fmaf(tx, u3, s3);

                float4* frow = (float4*)(out_feat + (size_t)p * W_FEAT);
                __stcs(frow + coff,
                       make_float4(s0 * vmask, s1 * vmask, s2 * vmask, s3 * vmask));
            }

            if (half == 0) {
                // grid_value: lanes 0..7 own a corner, butterfly-reduce.
                const int goffs8[8] = { 0, 1, N1, N1 + 1,
                                        N1 * N1, N1 * N1 + 1,
                                        N1 * N1 + N1, N1 * N1 + N1 + 1 };
                const float wv[8] = { wx0 * wyz0, wx0 * wyz1, wx0 * wyz2, wx0 * wyz3,
                                      tx  * wyz0, tx  * wyz1, tx  * wyz2, tx  * wyz3 };
                float gvv = 0.0f;
                if (lane < 8) gvv = wv[lane] * __ldg(gv + base + goffs8[lane]);
                gvv += __shfl_xor_sync(0xffffffffu, gvv, 4);
                gvv += __shfl_xor_sync(0xffffffffu, gvv, 2);
                gvv += __shfl_xor_sync(0xffffffffu, gvv, 1);
                if (lane == 0) out_val[p] = gvv * vmask;
            }
        }
    }
}

// Fallback (B > MAXB or tiny B): direct global-gather version, unsorted.
__global__ void __launch_bounds__(256) trilerp_kernel(
    const float* __restrict__ x,
    const float* __restrict__ gv,
    const float* __restrict__ gf,
    float* __restrict__ out_val,
    float* __restrict__ out_feat,
    int B)
{
    const int p = (blockIdx.x * blockDim.x + threadIdx.x) >> 5;
    const int lane = threadIdx.x & 31;
    if (p >= B) return;

    const float rx = (__ldg(x + p * 3 + 0) + 1.0f) * 32.0f;
    const float ry = (__ldg(x + p * 3 + 1) + 1.0f) * 32.0f;
    const float rz = (__ldg(x + p * 3 + 2) + 1.0f) * 32.0f;
    const bool valid = (rx >= 0.0f) && (rx <= 64.0f) && (ry >= 0.0f) &&
                       (ry <= 64.0f) && (rz >= 0.0f) && (rz <= 64.0f);
    const float vmask = valid ? 1.0f : 0.0f;
    int ix = (int)floorf(rx); ix = ix < 0 ? 0 : (ix > 63 ? 63 : ix);
    int iy = (int)floorf(ry); iy = iy < 0 ? 0 : (iy > 63 ? 63 : iy);
    int iz = (int)floorf(rz); iz = iz < 0 ? 0 : (iz > 63 ? 63 : iz);
    const float tx = rx - ix, ty = ry - iy, tz = rz - iz;
    const int base = (ix * N1 + iy) * N1 + iz;
    const float wx0 = 1.0f - tx, wy0 = 1.0f - ty, wz0 = 1.0f - tz;
    float w[8] = { wx0*wy0*wz0, wx0*wy0*tz, wx0*ty*wz0, wx0*ty*tz,
                   tx*wy0*wz0,  tx*wy0*tz,  tx*ty*wz0,  tx*ty*tz };
    const int offs[8] = { 0, 1, N1, N1+1, N1*N1, N1*N1+1, N1*N1+N1, N1*N1+N1+1 };

    float gvv = 0.0f;
    if (lane < 8) gvv = w[lane] * __ldg(gv + base + offs[lane]);
    gvv += __shfl_xor_sync(0xffffffffu, gvv, 4);
    gvv += __shfl_xor_sync(0xffffffffu, gvv, 2);
    gvv += __shfl_xor_sync(0xffffffffu, gvv, 1);
    if (lane == 0) out_val[p] = gvv * vmask;

    float a0=0,a1=0,a2=0,a3=0,b0=0,b1=0,b2=0,b3=0;
#pragma unroll
    for (int c = 0; c < 8; c++) {
        const float4* row = (const float4*)(gf + (size_t)(base + offs[c]) * W_FEAT);
        const float4 fa = __ldg(row + lane);
        const float4 fb = __ldg(row + lane + 32);
        const float wc = w[c];
        a0 = fmaf(wc, fa.x, a0); a1 = fmaf(wc, fa.y, a1);
        a2 = fmaf(wc, fa.z, a2); a3 = fmaf(wc, fa.w, a3);
        b0 = fmaf(wc, fb.x, b0); b1 = fmaf(wc, fb.y, b1);
        b2 = fmaf(wc, fb.z, b2); b3 = fmaf(wc, fb.w, b3);
    }
    float4* frow = (float4*)(out_feat + (size_t)p * W_FEAT);
    frow[lane]      = make_float4(a0*vmask, a1*vmask, a2*vmask, a3*vmask);
    frow[lane + 32] = make_float4(b0*vmask, b1*vmask, b2*vmask, b3*vmask);
}

extern "C" void kernel_launch(void* const* d_in, const int* in_sizes, int n_in,
                              void* d_out, int out_size)
{
    const float* x  = (const float*)d_in[0];
    const float* gv = (const float*)d_in[1];
    const float* gf = (const float*)d_in[2];
    float* out = (float*)d_out;

    const int B = in_sizes[0] / 3;
    float* out_val  = out;        // [B]
    float* out_feat = out + B;    // [B, 256]

    if (B <= MAXB && B >= NBINS) {
        histo_kernel<<<(B + 255) / 256, 256>>>(x, B);
        scan_kernel<<<1, 1024>>>();
        scatter_kernel<<<(B + 255) / 256, 256>>>(x, B);
        trilerp_persist_kernel<<<GRID_MAIN, 128>>>(gv, gf, out_val, out_feat);
    } else {
        const int blocks = (B + 7) / 8;
        trilerp_kernel<<<blocks, 256>>>(x, gv, gf, out_val, out_feat, B);
    }
}